// round 15
// baseline (speedup 1.0000x reference)
#include <cuda_runtime.h>
#include <cuda_fp16.h>
#include <cstdint>

#define BATCH 64
#define NQ 197
#define DIM 768
#define NH 12
#define HD 64
#define NUM_REL 732
#define MROWS (BATCH * NQ)   // 12608

#define XN (MROWS * DIM)
#define QKN (BATCH * NH * NQ * HD)
#define W1N (3 * DIM * DIM)
#define W2N (DIM * DIM)

static __device__ __half g_Xh[XN];
static __device__ __half g_W1h[W1N];
static __device__ __half g_W2h[W2N];
static __device__ __half g_Qh[QKN];
static __device__ __half g_Kh[QKN];
static __device__ __half g_Vh[QKN];
static __device__ __half g_AOh[XN];

// ---------------------------------------------------------------------------
// helpers
// ---------------------------------------------------------------------------
__device__ __forceinline__ uint32_t smem_u32(const void* p) {
    uint32_t a;
    asm("{ .reg .u64 t; cvta.to.shared.u64 t, %1; cvt.u32.u64 %0, t; }" : "=r"(a) : "l"(p));
    return a;
}

__device__ __forceinline__ void ldsm4(uint32_t* r, uint32_t addr) {
    asm volatile("ldmatrix.sync.aligned.m8n8.x4.shared.b16 {%0,%1,%2,%3}, [%4];"
                 : "=r"(r[0]), "=r"(r[1]), "=r"(r[2]), "=r"(r[3]) : "r"(addr));
}

__device__ __forceinline__ void ldsm4t(uint32_t* r, uint32_t addr) {
    asm volatile("ldmatrix.sync.aligned.m8n8.x4.trans.shared.b16 {%0,%1,%2,%3}, [%4];"
                 : "=r"(r[0]), "=r"(r[1]), "=r"(r[2]), "=r"(r[3]) : "r"(addr));
}

// fp16 HMMA, fp32 accumulate
__device__ __forceinline__ void mma16816(float* c, const uint32_t* a, const uint32_t* b) {
    asm volatile(
        "mma.sync.aligned.m16n8k16.row.col.f32.f16.f16.f32 "
        "{%0,%1,%2,%3}, {%4,%5,%6,%7}, {%8,%9}, {%0,%1,%2,%3};"
        : "+f"(c[0]), "+f"(c[1]), "+f"(c[2]), "+f"(c[3])
        : "r"(a[0]), "r"(a[1]), "r"(a[2]), "r"(a[3]), "r"(b[0]), "r"(b[1]));
}

__device__ __forceinline__ uint32_t cvt2h(float x, float y) {
    __half2 h = __floats2half2_rn(x, y);
    return *reinterpret_cast<uint32_t*>(&h);
}

__device__ __forceinline__ void cp16(uint32_t dst, const void* src, uint32_t srcbytes) {
    asm volatile("cp.async.cg.shared.global [%0], [%1], 16, %2;"
                 :: "r"(dst), "l"(src), "r"(srcbytes) : "memory");
}
#define CP_COMMIT() asm volatile("cp.async.commit_group;" ::: "memory")
#define CP_WAIT(N)  asm volatile("cp.async.wait_group %0;" :: "n"(N) : "memory")

// ---------------------------------------------------------------------------
// merged fp32 -> fp16 conversion (one launch for X, W1, W2)
// ---------------------------------------------------------------------------
#define XN4 (XN / 4)
#define W1N4 (W1N / 4)
#define W2N4 (W2N / 4)
#define CVT_TOTAL4 (XN4 + W1N4 + W2N4)

__global__ void cvt_all_kernel(const float* __restrict__ x, __half* __restrict__ xh,
                               const float* __restrict__ w1, __half* __restrict__ w1h,
                               const float* __restrict__ w2, __half* __restrict__ w2h) {
    int i = blockIdx.x * 256 + threadIdx.x;
    if (i >= CVT_TOTAL4) return;
    const float* in;
    __half* outp;
    int j = i;
    if (j < XN4) { in = x; outp = xh; }
    else if (j < XN4 + W1N4) { j -= XN4; in = w1; outp = w1h; }
    else { j -= XN4 + W1N4; in = w2; outp = w2h; }
    float4 v = reinterpret_cast<const float4*>(in)[j];
    reinterpret_cast<uint2*>(outp)[j] = make_uint2(cvt2h(v.x, v.y), cvt2h(v.z, v.w));
}

// ---------------------------------------------------------------------------
// single-fp16 GEMM: CTA 128x128, 8 warps (warp 64x32), BK=96 per stage,
// 2-stage cp.async, ONE sync per 96-K chunk (8 epochs), 2 CTAs/SM.
// 208-byte row stride (odd multiple of 16 -> ldmatrix conflict-free).
// ---------------------------------------------------------------------------
#define STRD 208                     // bytes per smem row (192 data + 16 pad)
#define TILEH (128 * STRD)           // 26624 B per matrix per stage
#define STGH  (2 * TILEH)            // 53248 B per stage (A + B)
#define GSH_TOTAL (2 * STGH)         // 106496 B (x2 CTAs = 212992 <= 228K)
#define NKT2 (DIM / 96)              // 8

template <typename Epi>
__global__ __launch_bounds__(256, 2)
void hgemm(const __half* __restrict__ Ah, const __half* __restrict__ Bh,
           int M, Epi epi) {
    extern __shared__ char smem[];
    const uint32_t sb = smem_u32(smem);
    const int tid = threadIdx.x;
    const int warp = tid >> 5;
    const int lane = tid & 31;
    const int wm = warp >> 2;
    const int wn = warp & 3;
    const int m0 = blockIdx.y * 128;
    const int n0 = blockIdx.x * 128;

    float acc[4][4][4];
#pragma unroll
    for (int i = 0; i < 4; i++)
#pragma unroll
        for (int j = 0; j < 4; j++)
#pragma unroll
            for (int k = 0; k < 4; k++) acc[i][j][k] = 0.f;

    uint32_t aoff[4], boff[2];
#pragma unroll
    for (int mf = 0; mf < 4; mf++)
        aoff[mf] = (uint32_t)((wm * 64 + mf * 16 + (lane & 15)) * STRD + (lane >> 4) * 16);
#pragma unroll
    for (int pr = 0; pr < 2; pr++)
        boff[pr] = (uint32_t)(TILEH +
                   (wn * 32 + pr * 16 + ((lane >> 4) * 8) + (lane & 7)) * STRD +
                   ((lane >> 3) & 1) * 16);

    // 3072 16B chunks per stage (1536 per matrix, 12 per 192B row): 12/thread
    auto load_stage = [&](int kt) {
        const uint32_t sbase = sb + (uint32_t)((kt & 1) * STGH);
#pragma unroll
        for (int i = 0; i < 12; i++) {
            int id = tid + 256 * i;              // 0..3071
            int mat = (id >= 1536) ? 1 : 0;
            int idm = id - mat * 1536;           // 0..1535
            int r = idm / 12;                    // 0..127
            int c4 = idm - r * 12;               // 0..11
            uint32_t dst = sbase + (uint32_t)(mat * TILEH + r * STRD + c4 * 16);
            if (mat == 0) {
                int m = m0 + r;
                int mc = (m < M) ? m : 0;
                uint32_t sz = (m < M) ? 16u : 0u;
                cp16(dst, Ah + (size_t)mc * DIM + kt * 96 + c4 * 8, sz);
            } else {
                cp16(dst, Bh + (size_t)(n0 + r) * DIM + kt * 96 + c4 * 8, 16u);
            }
        }
        CP_COMMIT();
    };

    auto compute = [&](int st) {
        const uint32_t sadd = sb + (uint32_t)(st * STGH);
#pragma unroll
        for (int ks = 0; ks < 6; ks++) {
            uint32_t bh[4][2];
#pragma unroll
            for (int pr = 0; pr < 2; pr++) {
                uint32_t t[4];
                ldsm4(t, sadd + boff[pr] + ks * 32);
                bh[2 * pr][0] = t[0]; bh[2 * pr][1] = t[1];
                bh[2 * pr + 1][0] = t[2]; bh[2 * pr + 1][1] = t[3];
            }
#pragma unroll
            for (int mf = 0; mf < 4; mf++) {
                uint32_t ah[4];
                ldsm4(ah, sadd + aoff[mf] + ks * 32);
#pragma unroll
                for (int nf = 0; nf < 4; nf++) mma16816(acc[mf][nf], ah, bh[nf]);
            }
        }
    };

    load_stage(0);

    for (int kt = 0; kt < NKT2; kt++) {
        CP_WAIT(0);
        __syncthreads();
        if (kt + 1 < NKT2) load_stage(kt + 1);
        compute(kt & 1);
    }

    const int g = lane >> 2;
    const int tig = lane & 3;
#pragma unroll
    for (int mf = 0; mf < 4; mf++) {
#pragma unroll
        for (int nf = 0; nf < 4; nf++) {
            int m = m0 + wm * 64 + mf * 16 + g;
            int n = n0 + wn * 32 + nf * 8 + tig * 2;
            if (m < M)     epi(m, n, make_float2(acc[mf][nf][0], acc[mf][nf][1]));
            if (m + 8 < M) epi(m + 8, n, make_float2(acc[mf][nf][2], acc[mf][nf][3]));
        }
    }
}

struct QKVEpiH {
    const float* qb;
    const float* vb;
    __half *Qh, *Kh, *Vh;
    __device__ __forceinline__ void operator()(int m, int n, float2 v) const {
        int part = n / DIM;
        int c = n - part * DIM;
        int h = c >> 6;
        int d = c & 63;
        int b = m / NQ;
        int r = m - b * NQ;
        size_t idx = ((size_t)((b * NH + h) * NQ + r)) * HD + d;
        if (part == 0) {
            *reinterpret_cast<uint32_t*>(Qh + idx) =
                cvt2h((v.x + qb[c]) * 0.125f, (v.y + qb[c + 1]) * 0.125f);
        } else if (part == 1) {
            *reinterpret_cast<uint32_t*>(Kh + idx) = cvt2h(v.x, v.y);
        } else {
            *reinterpret_cast<uint32_t*>(Vh + idx) = cvt2h(v.x + vb[c], v.y + vb[c + 1]);
        }
    }
};

struct ProjEpi2 {
    const float* pb;
    float* out;
    __device__ __forceinline__ void operator()(int m, int n, float2 v) const {
        v.x += pb[n];
        v.y += pb[n + 1];
        *reinterpret_cast<float2*>(out + (size_t)m * DIM + n) = v;
    }
};

// ---------------------------------------------------------------------------
// Tensor-core attention, single fp16. Two CTAs per (b,h): 224 threads,
// 7 warps each, each warp owns one q-block (half 0: blocks 0-6, half 1: 7-12).
// smem 92.8 KB -> 2 CTAs/SM, 14 warps/SM.
// ---------------------------------------------------------------------------
#define ATHREADS 224
#define NQP 208
#define KSTR_B 144
#define AMAT_B (NQP * KSTR_B)
#define ASMEM_TOTAL (3 * AMAT_B + NUM_REL * 4)   // 92784

__global__ __launch_bounds__(ATHREADS, 2)
void attn_mma(const __half* __restrict__ Qh,
              const __half* __restrict__ Kh, const __half* __restrict__ Vh,
              const float* __restrict__ tabg, const int* __restrict__ ridx,
              __half* __restrict__ AOh) {
    extern __shared__ char sm[];
    const uint32_t sb = smem_u32(sm);
    const uint32_t sQ = sb;
    const uint32_t sK = sb + 1 * AMAT_B;
    const uint32_t sV = sb + 2 * AMAT_B;
    float* tab = reinterpret_cast<float*>(sm + 3 * AMAT_B);

    const int bh = blockIdx.x >> 1;
    const int half = blockIdx.x & 1;
    const int h = bh % NH;
    const int b = bh / NH;
    const int tid = threadIdx.x;
    const int warp = tid >> 5;           // 0..6
    const int lane = tid & 31;
    const int g = lane >> 2;
    const int tig = lane & 3;
    const size_t base = (size_t)bh * NQ * HD;

    // zero pad rows 197..207 in all three arrays
    for (int i = tid; i < 11 * 9; i += ATHREADS) {
        int r = 197 + i / 9;
        int c = i % 9;
        uint32_t off = (uint32_t)(r * KSTR_B + c * 16);
#pragma unroll
        for (int a = 0; a < 3; a++)
            *reinterpret_cast<uint4*>(sm + a * AMAT_B + off) = make_uint4(0u, 0u, 0u, 0u);
    }
    for (int c = tid; c < NQ * 8; c += ATHREADS) {
        int r = c >> 3;
        int col = c & 7;
        uint32_t doff = (uint32_t)(r * KSTR_B + col * 16);
        size_t ga = base + (size_t)r * HD + col * 8;
        cp16(sQ + doff, Qh + ga, 16u);
        cp16(sK + doff, Kh + ga, 16u);
        cp16(sV + doff, Vh + ga, 16u);
    }
    CP_COMMIT();
    for (int i = tid; i < NUM_REL; i += ATHREADS) tab[i] = tabg[i * NH + h];
    CP_WAIT(0);
    __syncthreads();

    const int blk = half * 7 + warp;     // 0..13; 13 is invalid
    if (blk < 13) {
        float s[26][4];
#pragma unroll
        for (int nc = 0; nc < 26; nc++)
#pragma unroll
            for (int e = 0; e < 4; e++) s[nc][e] = 0.f;

        const uint32_t qrow = (uint32_t)((blk * 16 + (lane & 15)) * KSTR_B + (lane >> 4) * 16);
        const uint32_t krow = (uint32_t)(((lane >> 4) * 8 + (lane & 7)) * KSTR_B + ((lane >> 3) & 1) * 16);

#pragma unroll
        for (int kc = 0; kc < 4; kc++) {
            uint32_t qh[4];
            ldsm4(qh, sQ + qrow + kc * 32);
#pragma unroll
            for (int np = 0; np < 13; np++) {
                uint32_t th[4];
                ldsm4(th, sK + krow + (uint32_t)(np * 16 * KSTR_B) + kc * 32);
                mma16816(s[2 * np],     qh, th);
                mma16816(s[2 * np + 1], qh, th + 2);
            }
        }

        const int q0 = blk * 16 + g;
        const int q1 = q0 + 8;
        const int* r0 = ridx + (size_t)min(q0, NQ - 1) * NQ;
        const int* r1 = ridx + (size_t)min(q1, NQ - 1) * NQ;
#pragma unroll
        for (int nc = 0; nc < 26; nc++) {
            int n0 = nc * 8 + tig * 2;
            if (n0 < NQ) { s[nc][0] += tab[r0[n0]]; s[nc][2] += tab[r1[n0]]; }
            else         { s[nc][0] = -1e30f;       s[nc][2] = -1e30f; }
            int n1 = n0 + 1;
            if (n1 < NQ) { s[nc][1] += tab[r0[n1]]; s[nc][3] += tab[r1[n1]]; }
            else         { s[nc][1] = -1e30f;       s[nc][3] = -1e30f; }
        }

        float mx0 = -1e30f, mx1 = -1e30f;
#pragma unroll
        for (int nc = 0; nc < 26; nc++) {
            mx0 = fmaxf(mx0, fmaxf(s[nc][0], s[nc][1]));
            mx1 = fmaxf(mx1, fmaxf(s[nc][2], s[nc][3]));
        }
        mx0 = fmaxf(mx0, __shfl_xor_sync(0xffffffffu, mx0, 1));
        mx0 = fmaxf(mx0, __shfl_xor_sync(0xffffffffu, mx0, 2));
        mx1 = fmaxf(mx1, __shfl_xor_sync(0xffffffffu, mx1, 1));
        mx1 = fmaxf(mx1, __shfl_xor_sync(0xffffffffu, mx1, 2));

        float sum0 = 0.f, sum1 = 0.f;
#pragma unroll
        for (int nc = 0; nc < 26; nc++) {
            s[nc][0] = __expf(s[nc][0] - mx0);
            s[nc][1] = __expf(s[nc][1] - mx0);
            s[nc][2] = __expf(s[nc][2] - mx1);
            s[nc][3] = __expf(s[nc][3] - mx1);
            sum0 += s[nc][0] + s[nc][1];
            sum1 += s[nc][2] + s[nc][3];
        }
        sum0 += __shfl_xor_sync(0xffffffffu, sum0, 1);
        sum0 += __shfl_xor_sync(0xffffffffu, sum0, 2);
        sum1 += __shfl_xor_sync(0xffffffffu, sum1, 1);
        sum1 += __shfl_xor_sync(0xffffffffu, sum1, 2);
        float inv0 = __frcp_rn(sum0);
        float inv1 = __frcp_rn(sum1);
#pragma unroll
        for (int nc = 0; nc < 26; nc++) {
            s[nc][0] *= inv0; s[nc][1] *= inv0;
            s[nc][2] *= inv1; s[nc][3] *= inv1;
        }

        float o[8][4];
#pragma unroll
        for (int nd = 0; nd < 8; nd++)
#pragma unroll
            for (int e = 0; e < 4; e++) o[nd][e] = 0.f;

        const uint32_t vrow = (uint32_t)((((lane >> 3) & 1) * 8 + (lane & 7)) * KSTR_B + (lane >> 4) * 16);

#pragma unroll
        for (int kc = 0; kc < 13; kc++) {
            uint32_t ph[4];
            ph[0] = cvt2h(s[2 * kc][0],     s[2 * kc][1]);
            ph[1] = cvt2h(s[2 * kc][2],     s[2 * kc][3]);
            ph[2] = cvt2h(s[2 * kc + 1][0], s[2 * kc + 1][1]);
            ph[3] = cvt2h(s[2 * kc + 1][2], s[2 * kc + 1][3]);
#pragma unroll
            for (int dg = 0; dg < 4; dg++) {
                uint32_t vh4[4];
                ldsm4t(vh4, sV + vrow + (uint32_t)(kc * 16 * KSTR_B) + dg * 32);
                mma16816(o[2 * dg],     ph, vh4);
                mma16816(o[2 * dg + 1], ph, vh4 + 2);
            }
        }

        if (q0 < NQ) {
            size_t ob = ((size_t)(b * NQ + q0) * NH + h) * HD + tig * 2;
#pragma unroll
            for (int nd = 0; nd < 8; nd++)
                *reinterpret_cast<uint32_t*>(AOh + ob + nd * 8) = cvt2h(o[nd][0], o[nd][1]);
        }
        if (q1 < NQ) {
            size_t ob = ((size_t)(b * NQ + q1) * NH + h) * HD + tig * 2;
#pragma unroll
            for (int nd = 0; nd < 8; nd++)
                *reinterpret_cast<uint32_t*>(AOh + ob + nd * 8) = cvt2h(o[nd][2], o[nd][3]);
        }
    }
}

// ---------------------------------------------------------------------------
extern "C" void kernel_launch(void* const* d_in, const int* in_sizes, int n_in,
                              void* d_out, int out_size) {
    const float* x      = (const float*)d_in[0];
    const float* qkv_w  = (const float*)d_in[1];
    const float* q_bias = (const float*)d_in[2];
    const float* v_bias = (const float*)d_in[3];
    const float* rpb    = (const float*)d_in[4];
    const float* proj_w = (const float*)d_in[5];
    const float* proj_b = (const float*)d_in[6];
    const int*   ridx   = (const int*)d_in[7];
    float* out = (float*)d_out;

    __half *Xh, *W1h, *W2h, *Qh, *Kh, *Vh, *AOh;
    cudaGetSymbolAddress((void**)&Xh, g_Xh);
    cudaGetSymbolAddress((void**)&W1h, g_W1h);
    cudaGetSymbolAddress((void**)&W2h, g_W2h);
    cudaGetSymbolAddress((void**)&Qh, g_Qh);
    cudaGetSymbolAddress((void**)&Kh, g_Kh);
    cudaGetSymbolAddress((void**)&Vh, g_Vh);
    cudaGetSymbolAddress((void**)&AOh, g_AOh);

    cudaFuncSetAttribute(hgemm<QKVEpiH>, cudaFuncAttributeMaxDynamicSharedMemorySize, GSH_TOTAL);
    cudaFuncSetAttribute(hgemm<ProjEpi2>, cudaFuncAttributeMaxDynamicSharedMemorySize, GSH_TOTAL);
    cudaFuncSetAttribute(attn_mma, cudaFuncAttributeMaxDynamicSharedMemorySize, ASMEM_TOTAL);

    // 0) merged fp32 -> fp16 conversion (one launch)
    cvt_all_kernel<<<(CVT_TOTAL4 + 255) / 256, 256>>>(x, Xh, qkv_w, W1h, proj_w, W2h);

    // 1) fused QKV projection (single fp16, BK=96 epochs)
    QKVEpiH e1{q_bias, v_bias, Qh, Kh, Vh};
    hgemm<QKVEpiH><<<dim3(3 * DIM / 128, (MROWS + 127) / 128), 256, GSH_TOTAL>>>(
        Xh, W1h, MROWS, e1);

    // 2) attention: 2 CTAs per (b,h), 7 warps each, 2 CTAs/SM
    attn_mma<<<BATCH * NH * 2, ATHREADS, ASMEM_TOTAL>>>(Qh, Kh, Vh, rpb, ridx, AOh);

    // 3) output projection (single fp16, BK=96 epochs)
    ProjEpi2 e2{proj_b, out};
    hgemm<ProjEpi2><<<dim3(DIM / 128, (MROWS + 127) / 128), 256, GSH_TOTAL>>>(
        AOh, W2h, MROWS, e2);
}

// round 16
// speedup vs baseline: 1.0126x; 1.0126x over previous
#include <cuda_runtime.h>
#include <cuda_fp16.h>
#include <cstdint>

#define BATCH 64
#define NQ 197
#define DIM 768
#define NH 12
#define HD 64
#define NUM_REL 732
#define MROWS (BATCH * NQ)   // 12608

#define XN (MROWS * DIM)
#define QKN (BATCH * NH * NQ * HD)
#define W1N (3 * DIM * DIM)
#define W2N (DIM * DIM)

static __device__ __half g_Xh[XN];
static __device__ __half g_W1h[W1N];
static __device__ __half g_W2h[W2N];
static __device__ __half g_Qh[QKN];
static __device__ __half g_Kh[QKN];
static __device__ __half g_Vh[QKN];
static __device__ __half g_AOh[XN];

// ---------------------------------------------------------------------------
// helpers
// ---------------------------------------------------------------------------
__device__ __forceinline__ uint32_t smem_u32(const void* p) {
    uint32_t a;
    asm("{ .reg .u64 t; cvta.to.shared.u64 t, %1; cvt.u32.u64 %0, t; }" : "=r"(a) : "l"(p));
    return a;
}

__device__ __forceinline__ void ldsm4(uint32_t* r, uint32_t addr) {
    asm volatile("ldmatrix.sync.aligned.m8n8.x4.shared.b16 {%0,%1,%2,%3}, [%4];"
                 : "=r"(r[0]), "=r"(r[1]), "=r"(r[2]), "=r"(r[3]) : "r"(addr));
}

__device__ __forceinline__ void ldsm4t(uint32_t* r, uint32_t addr) {
    asm volatile("ldmatrix.sync.aligned.m8n8.x4.trans.shared.b16 {%0,%1,%2,%3}, [%4];"
                 : "=r"(r[0]), "=r"(r[1]), "=r"(r[2]), "=r"(r[3]) : "r"(addr));
}

// fp16 HMMA, fp32 accumulate
__device__ __forceinline__ void mma16816(float* c, const uint32_t* a, const uint32_t* b) {
    asm volatile(
        "mma.sync.aligned.m16n8k16.row.col.f32.f16.f16.f32 "
        "{%0,%1,%2,%3}, {%4,%5,%6,%7}, {%8,%9}, {%0,%1,%2,%3};"
        : "+f"(c[0]), "+f"(c[1]), "+f"(c[2]), "+f"(c[3])
        : "r"(a[0]), "r"(a[1]), "r"(a[2]), "r"(a[3]), "r"(b[0]), "r"(b[1]));
}

__device__ __forceinline__ uint32_t cvt2h(float x, float y) {
    __half2 h = __floats2half2_rn(x, y);
    return *reinterpret_cast<uint32_t*>(&h);
}

__device__ __forceinline__ void cp16(uint32_t dst, const void* src, uint32_t srcbytes) {
    asm volatile("cp.async.cg.shared.global [%0], [%1], 16, %2;"
                 :: "r"(dst), "l"(src), "r"(srcbytes) : "memory");
}
#define CP_COMMIT() asm volatile("cp.async.commit_group;" ::: "memory")
#define CP_WAIT(N)  asm volatile("cp.async.wait_group %0;" :: "n"(N) : "memory")

// ---------------------------------------------------------------------------
// merged fp32 -> fp16 conversion (one launch for X, W1, W2)
// ---------------------------------------------------------------------------
#define XN4 (XN / 4)
#define W1N4 (W1N / 4)
#define W2N4 (W2N / 4)
#define CVT_TOTAL4 (XN4 + W1N4 + W2N4)

__global__ void cvt_all_kernel(const float* __restrict__ x, __half* __restrict__ xh,
                               const float* __restrict__ w1, __half* __restrict__ w1h,
                               const float* __restrict__ w2, __half* __restrict__ w2h) {
    int i = blockIdx.x * 256 + threadIdx.x;
    if (i >= CVT_TOTAL4) return;
    const float* in;
    __half* outp;
    int j = i;
    if (j < XN4) { in = x; outp = xh; }
    else if (j < XN4 + W1N4) { j -= XN4; in = w1; outp = w1h; }
    else { j -= XN4 + W1N4; in = w2; outp = w2h; }
    float4 v = reinterpret_cast<const float4*>(in)[j];
    reinterpret_cast<uint2*>(outp)[j] = make_uint2(cvt2h(v.x, v.y), cvt2h(v.z, v.w));
}

// ---------------------------------------------------------------------------
// single-fp16 GEMM: CTA 128x128, 8 warps (warp 64x32), BK=64 per stage,
// 3-stage cp.async (CP_WAIT(1): 2 compute epochs of load slack),
// ONE sync per 64-K chunk (12 epochs), 2 CTAs/SM.
// ---------------------------------------------------------------------------
#define STRD 144                     // bytes per smem row (128 data + 16 pad)
#define TILEH (128 * STRD)           // 18432 B per matrix per stage
#define STGH  (2 * TILEH)            // 36864 B per stage (A + B)
#define GSH_TOTAL (3 * STGH)         // 110592 B (x2 CTAs = 221184 <= 228K)
#define NKT2 (DIM / 64)              // 12

template <typename Epi>
__global__ __launch_bounds__(256, 2)
void hgemm(const __half* __restrict__ Ah, const __half* __restrict__ Bh,
           int M, Epi epi) {
    extern __shared__ char smem[];
    const uint32_t sb = smem_u32(smem);
    const int tid = threadIdx.x;
    const int warp = tid >> 5;
    const int lane = tid & 31;
    const int wm = warp >> 2;
    const int wn = warp & 3;
    const int m0 = blockIdx.y * 128;
    const int n0 = blockIdx.x * 128;

    float acc[4][4][4];
#pragma unroll
    for (int i = 0; i < 4; i++)
#pragma unroll
        for (int j = 0; j < 4; j++)
#pragma unroll
            for (int k = 0; k < 4; k++) acc[i][j][k] = 0.f;

    uint32_t aoff[4], boff[2];
#pragma unroll
    for (int mf = 0; mf < 4; mf++)
        aoff[mf] = (uint32_t)((wm * 64 + mf * 16 + (lane & 15)) * STRD + (lane >> 4) * 16);
#pragma unroll
    for (int pr = 0; pr < 2; pr++)
        boff[pr] = (uint32_t)(TILEH +
                   (wn * 32 + pr * 16 + ((lane >> 4) * 8) + (lane & 7)) * STRD +
                   ((lane >> 3) & 1) * 16);

    // 2048 16B chunks per stage (1024 per matrix, 8 per 128B row): 8/thread
    auto load_stage = [&](int kt) {
        const uint32_t sbase = sb + (uint32_t)((kt % 3) * STGH);
#pragma unroll
        for (int i = 0; i < 8; i++) {
            int id = tid + 256 * i;              // 0..2047
            int mat = id >> 10;                  // 0 = A, 1 = B
            int r = (id & 1023) >> 3;            // 0..127
            int c4 = id & 7;
            uint32_t dst = sbase + (uint32_t)(mat * TILEH + r * STRD + c4 * 16);
            if (mat == 0) {
                int m = m0 + r;
                int mc = (m < M) ? m : 0;
                uint32_t sz = (m < M) ? 16u : 0u;
                cp16(dst, Ah + (size_t)mc * DIM + kt * 64 + c4 * 8, sz);
            } else {
                cp16(dst, Bh + (size_t)(n0 + r) * DIM + kt * 64 + c4 * 8, 16u);
            }
        }
        CP_COMMIT();
    };

    auto compute = [&](int st) {
        const uint32_t sadd = sb + (uint32_t)(st * STGH);
#pragma unroll
        for (int ks = 0; ks < 4; ks++) {
            uint32_t bh[4][2];
#pragma unroll
            for (int pr = 0; pr < 2; pr++) {
                uint32_t t[4];
                ldsm4(t, sadd + boff[pr] + ks * 32);
                bh[2 * pr][0] = t[0]; bh[2 * pr][1] = t[1];
                bh[2 * pr + 1][0] = t[2]; bh[2 * pr + 1][1] = t[3];
            }
#pragma unroll
            for (int mf = 0; mf < 4; mf++) {
                uint32_t ah[4];
                ldsm4(ah, sadd + aoff[mf] + ks * 32);
#pragma unroll
                for (int nf = 0; nf < 4; nf++) mma16816(acc[mf][nf], ah, bh[nf]);
            }
        }
    };

    load_stage(0);
    load_stage(1);

    for (int kt = 0; kt < NKT2; kt++) {
        CP_WAIT(1);              // stage kt resident (1 group may stay in flight)
        __syncthreads();         // compute(kt-1) done -> stage (kt+2)%3 free
        if (kt + 2 < NKT2) load_stage(kt + 2);
        compute(kt % 3);
    }

    const int g = lane >> 2;
    const int tig = lane & 3;
#pragma unroll
    for (int mf = 0; mf < 4; mf++) {
#pragma unroll
        for (int nf = 0; nf < 4; nf++) {
            int m = m0 + wm * 64 + mf * 16 + g;
            int n = n0 + wn * 32 + nf * 8 + tig * 2;
            if (m < M)     epi(m, n, make_float2(acc[mf][nf][0], acc[mf][nf][1]));
            if (m + 8 < M) epi(m + 8, n, make_float2(acc[mf][nf][2], acc[mf][nf][3]));
        }
    }
}

struct QKVEpiH {
    const float* qb;
    const float* vb;
    __half *Qh, *Kh, *Vh;
    __device__ __forceinline__ void operator()(int m, int n, float2 v) const {
        int part = n / DIM;
        int c = n - part * DIM;
        int h = c >> 6;
        int d = c & 63;
        int b = m / NQ;
        int r = m - b * NQ;
        size_t idx = ((size_t)((b * NH + h) * NQ + r)) * HD + d;
        if (part == 0) {
            *reinterpret_cast<uint32_t*>(Qh + idx) =
                cvt2h((v.x + qb[c]) * 0.125f, (v.y + qb[c + 1]) * 0.125f);
        } else if (part == 1) {
            *reinterpret_cast<uint32_t*>(Kh + idx) = cvt2h(v.x, v.y);
        } else {
            *reinterpret_cast<uint32_t*>(Vh + idx) = cvt2h(v.x + vb[c], v.y + vb[c + 1]);
        }
    }
};

struct ProjEpi2 {
    const float* pb;
    float* out;
    __device__ __forceinline__ void operator()(int m, int n, float2 v) const {
        v.x += pb[n];
        v.y += pb[n + 1];
        *reinterpret_cast<float2*>(out + (size_t)m * DIM + n) = v;
    }
};

// ---------------------------------------------------------------------------
// Tensor-core attention, single fp16. 13 warps, 1 q-block per warp.
// V load overlapped with S phase (separate cp.async group).
// ---------------------------------------------------------------------------
#define ATHREADS 416
#define NQP 208
#define KSTR_B 144
#define AMAT_B (NQP * KSTR_B)
#define ASMEM_TOTAL (3 * AMAT_B + NUM_REL * 4)   // 92784

__global__ __launch_bounds__(ATHREADS, 1)
void attn_mma(const __half* __restrict__ Qh,
              const __half* __restrict__ Kh, const __half* __restrict__ Vh,
              const float* __restrict__ tabg, const int* __restrict__ ridx,
              __half* __restrict__ AOh) {
    extern __shared__ char sm[];
    const uint32_t sb = smem_u32(sm);
    const uint32_t sQ = sb;
    const uint32_t sK = sb + 1 * AMAT_B;
    const uint32_t sV = sb + 2 * AMAT_B;
    float* tab = reinterpret_cast<float*>(sm + 3 * AMAT_B);

    const int bh = blockIdx.x;
    const int h = bh % NH;
    const int b = bh / NH;
    const int tid = threadIdx.x;
    const int warp = tid >> 5;
    const int lane = tid & 31;
    const int g = lane >> 2;
    const int tig = lane & 3;
    const size_t base = (size_t)bh * NQ * HD;

    // zero pad rows 197..207 (STS; ordered by the first __syncthreads)
    for (int i = tid; i < 11 * 9; i += ATHREADS) {
        int r = 197 + i / 9;
        int c = i % 9;
        uint32_t off = (uint32_t)(r * KSTR_B + c * 16);
#pragma unroll
        for (int a = 0; a < 3; a++)
            *reinterpret_cast<uint4*>(sm + a * AMAT_B + off) = make_uint4(0u, 0u, 0u, 0u);
    }
    // group 1: Q + K
    for (int c = tid; c < NQ * 8; c += ATHREADS) {
        int r = c >> 3;
        int col = c & 7;
        uint32_t doff = (uint32_t)(r * KSTR_B + col * 16);
        size_t ga = base + (size_t)r * HD + col * 8;
        cp16(sQ + doff, Qh + ga, 16u);
        cp16(sK + doff, Kh + ga, 16u);
    }
    CP_COMMIT();
    // group 2: V (completes under the S phase)
    for (int c = tid; c < NQ * 8; c += ATHREADS) {
        int r = c >> 3;
        int col = c & 7;
        uint32_t doff = (uint32_t)(r * KSTR_B + col * 16);
        cp16(sV + doff, Vh + base + (size_t)r * HD + col * 8, 16u);
    }
    CP_COMMIT();
    for (int i = tid; i < NUM_REL; i += ATHREADS) tab[i] = tabg[i * NH + h];
    CP_WAIT(1);                       // Q + K resident; V still in flight
    __syncthreads();

    {
        const int blk = warp;
        float s[26][4];
#pragma unroll
        for (int nc = 0; nc < 26; nc++)
#pragma unroll
            for (int e = 0; e < 4; e++) s[nc][e] = 0.f;

        const uint32_t qrow = (uint32_t)((blk * 16 + (lane & 15)) * KSTR_B + (lane >> 4) * 16);
        const uint32_t krow = (uint32_t)(((lane >> 4) * 8 + (lane & 7)) * KSTR_B + ((lane >> 3) & 1) * 16);

#pragma unroll
        for (int kc = 0; kc < 4; kc++) {
            uint32_t qh[4];
            ldsm4(qh, sQ + qrow + kc * 32);
#pragma unroll
            for (int np = 0; np < 13; np++) {
                uint32_t th[4];
                ldsm4(th, sK + krow + (uint32_t)(np * 16 * KSTR_B) + kc * 32);
                mma16816(s[2 * np],     qh, th);
                mma16816(s[2 * np + 1], qh, th + 2);
            }
        }

        const int q0 = blk * 16 + g;
        const int q1 = q0 + 8;
        const int* r0 = ridx + (size_t)min(q0, NQ - 1) * NQ;
        const int* r1 = ridx + (size_t)min(q1, NQ - 1) * NQ;
#pragma unroll
        for (int nc = 0; nc < 26; nc++) {
            int n0 = nc * 8 + tig * 2;
            if (n0 < NQ) { s[nc][0] += tab[r0[n0]]; s[nc][2] += tab[r1[n0]]; }
            else         { s[nc][0] = -1e30f;       s[nc][2] = -1e30f; }
            int n1 = n0 + 1;
            if (n1 < NQ) { s[nc][1] += tab[r0[n1]]; s[nc][3] += tab[r1[n1]]; }
            else         { s[nc][1] = -1e30f;       s[nc][3] = -1e30f; }
        }

        float mx0 = -1e30f, mx1 = -1e30f;
#pragma unroll
        for (int nc = 0; nc < 26; nc++) {
            mx0 = fmaxf(mx0, fmaxf(s[nc][0], s[nc][1]));
            mx1 = fmaxf(mx1, fmaxf(s[nc][2], s[nc][3]));
        }
        mx0 = fmaxf(mx0, __shfl_xor_sync(0xffffffffu, mx0, 1));
        mx0 = fmaxf(mx0, __shfl_xor_sync(0xffffffffu, mx0, 2));
        mx1 = fmaxf(mx1, __shfl_xor_sync(0xffffffffu, mx1, 1));
        mx1 = fmaxf(mx1, __shfl_xor_sync(0xffffffffu, mx1, 2));

        float sum0 = 0.f, sum1 = 0.f;
#pragma unroll
        for (int nc = 0; nc < 26; nc++) {
            s[nc][0] = __expf(s[nc][0] - mx0);
            s[nc][1] = __expf(s[nc][1] - mx0);
            s[nc][2] = __expf(s[nc][2] - mx1);
            s[nc][3] = __expf(s[nc][3] - mx1);
            sum0 += s[nc][0] + s[nc][1];
            sum1 += s[nc][2] + s[nc][3];
        }
        sum0 += __shfl_xor_sync(0xffffffffu, sum0, 1);
        sum0 += __shfl_xor_sync(0xffffffffu, sum0, 2);
        sum1 += __shfl_xor_sync(0xffffffffu, sum1, 1);
        sum1 += __shfl_xor_sync(0xffffffffu, sum1, 2);
        float inv0 = __frcp_rn(sum0);
        float inv1 = __frcp_rn(sum1);
#pragma unroll
        for (int nc = 0; nc < 26; nc++) {
            s[nc][0] *= inv0; s[nc][1] *= inv0;
            s[nc][2] *= inv1; s[nc][3] *= inv1;
        }

        // V must be resident and visible to all threads before PV
        CP_WAIT(0);
        __syncthreads();

        float o[8][4];
#pragma unroll
        for (int nd = 0; nd < 8; nd++)
#pragma unroll
            for (int e = 0; e < 4; e++) o[nd][e] = 0.f;

        const uint32_t vrow = (uint32_t)((((lane >> 3) & 1) * 8 + (lane & 7)) * KSTR_B + (lane >> 4) * 16);

#pragma unroll
        for (int kc = 0; kc < 13; kc++) {
            uint32_t ph[4];
            ph[0] = cvt2h(s[2 * kc][0],     s[2 * kc][1]);
            ph[1] = cvt2h(s[2 * kc][2],     s[2 * kc][3]);
            ph[2] = cvt2h(s[2 * kc + 1][0], s[2 * kc + 1][1]);
            ph[3] = cvt2h(s[2 * kc + 1][2], s[2 * kc + 1][3]);
#pragma unroll
            for (int dg = 0; dg < 4; dg++) {
                uint32_t vh4[4];
                ldsm4t(vh4, sV + vrow + (uint32_t)(kc * 16 * KSTR_B) + dg * 32);
                mma16816(o[2 * dg],     ph, vh4);
                mma16816(o[2 * dg + 1], ph, vh4 + 2);
            }
        }

        if (q0 < NQ) {
            size_t ob = ((size_t)(b * NQ + q0) * NH + h) * HD + tig * 2;
#pragma unroll
            for (int nd = 0; nd < 8; nd++)
                *reinterpret_cast<uint32_t*>(AOh + ob + nd * 8) = cvt2h(o[nd][0], o[nd][1]);
        }
        if (q1 < NQ) {
            size_t ob = ((size_t)(b * NQ + q1) * NH + h) * HD + tig * 2;
#pragma unroll
            for (int nd = 0; nd < 8; nd++)
                *reinterpret_cast<uint32_t*>(AOh + ob + nd * 8) = cvt2h(o[nd][2], o[nd][3]);
        }
    }
}

// ---------------------------------------------------------------------------
extern "C" void kernel_launch(void* const* d_in, const int* in_sizes, int n_in,
                              void* d_out, int out_size) {
    const float* x      = (const float*)d_in[0];
    const float* qkv_w  = (const float*)d_in[1];
    const float* q_bias = (const float*)d_in[2];
    const float* v_bias = (const float*)d_in[3];
    const float* rpb    = (const float*)d_in[4];
    const float* proj_w = (const float*)d_in[5];
    const float* proj_b = (const float*)d_in[6];
    const int*   ridx   = (const int*)d_in[7];
    float* out = (float*)d_out;

    __half *Xh, *W1h, *W2h, *Qh, *Kh, *Vh, *AOh;
    cudaGetSymbolAddress((void**)&Xh, g_Xh);
    cudaGetSymbolAddress((void**)&W1h, g_W1h);
    cudaGetSymbolAddress((void**)&W2h, g_W2h);
    cudaGetSymbolAddress((void**)&Qh, g_Qh);
    cudaGetSymbolAddress((void**)&Kh, g_Kh);
    cudaGetSymbolAddress((void**)&Vh, g_Vh);
    cudaGetSymbolAddress((void**)&AOh, g_AOh);

    cudaFuncSetAttribute(hgemm<QKVEpiH>, cudaFuncAttributeMaxDynamicSharedMemorySize, GSH_TOTAL);
    cudaFuncSetAttribute(hgemm<ProjEpi2>, cudaFuncAttributeMaxDynamicSharedMemorySize, GSH_TOTAL);
    cudaFuncSetAttribute(attn_mma, cudaFuncAttributeMaxDynamicSharedMemorySize, ASMEM_TOTAL);

    // 0) merged fp32 -> fp16 conversion (one launch)
    cvt_all_kernel<<<(CVT_TOTAL4 + 255) / 256, 256>>>(x, Xh, qkv_w, W1h, proj_w, W2h);

    // 1) fused QKV projection (single fp16, BK=64, 3-stage)
    QKVEpiH e1{q_bias, v_bias, Qh, Kh, Vh};
    hgemm<QKVEpiH><<<dim3(3 * DIM / 128, (MROWS + 127) / 128), 256, GSH_TOTAL>>>(
        Xh, W1h, MROWS, e1);

    // 2) attention (single fp16, V overlapped with S phase)
    attn_mma<<<BATCH * NH, ATHREADS, ASMEM_TOTAL>>>(Qh, Kh, Vh, rpb, ridx, AOh);

    // 3) output projection (single fp16, BK=64, 3-stage)
    ProjEpi2 e2{proj_b, out};
    hgemm<ProjEpi2><<<dim3(DIM / 128, (MROWS + 127) / 128), 256, GSH_TOTAL>>>(
        AOh, W2h, MROWS, e2);
}

// round 17
// speedup vs baseline: 1.0603x; 1.0471x over previous
#include <cuda_runtime.h>
#include <cuda_fp16.h>
#include <cstdint>

#define BATCH 64
#define NQ 197
#define DIM 768
#define NH 12
#define HD 64
#define NUM_REL 732
#define MROWS (BATCH * NQ)   // 12608

#define XN (MROWS * DIM)
#define QKN (BATCH * NH * NQ * HD)
#define W1N (3 * DIM * DIM)
#define W2N (DIM * DIM)

#define NQP 208
#define BPQ 104               // fp16x2 bias pairs per q-row

static __device__ __half g_Xh[XN];
static __device__ __half g_W1h[W1N];
static __device__ __half g_W2h[W2N];
static __device__ __half g_Qh[QKN];
static __device__ __half g_Kh[QKN];
static __device__ __half g_Vh[QKN];
static __device__ __half g_AOh[XN];
static __device__ uint32_t g_biasP[NH * NQP * BPQ];

// ---------------------------------------------------------------------------
// helpers
// ---------------------------------------------------------------------------
__device__ __forceinline__ uint32_t smem_u32(const void* p) {
    uint32_t a;
    asm("{ .reg .u64 t; cvta.to.shared.u64 t, %1; cvt.u32.u64 %0, t; }" : "=r"(a) : "l"(p));
    return a;
}

__device__ __forceinline__ void ldsm4(uint32_t* r, uint32_t addr) {
    asm volatile("ldmatrix.sync.aligned.m8n8.x4.shared.b16 {%0,%1,%2,%3}, [%4];"
                 : "=r"(r[0]), "=r"(r[1]), "=r"(r[2]), "=r"(r[3]) : "r"(addr));
}

__device__ __forceinline__ void ldsm4t(uint32_t* r, uint32_t addr) {
    asm volatile("ldmatrix.sync.aligned.m8n8.x4.trans.shared.b16 {%0,%1,%2,%3}, [%4];"
                 : "=r"(r[0]), "=r"(r[1]), "=r"(r[2]), "=r"(r[3]) : "r"(addr));
}

// fp16 HMMA, fp32 accumulate
__device__ __forceinline__ void mma16816(float* c, const uint32_t* a, const uint32_t* b) {
    asm volatile(
        "mma.sync.aligned.m16n8k16.row.col.f32.f16.f16.f32 "
        "{%0,%1,%2,%3}, {%4,%5,%6,%7}, {%8,%9}, {%0,%1,%2,%3};"
        : "+f"(c[0]), "+f"(c[1]), "+f"(c[2]), "+f"(c[3])
        : "r"(a[0]), "r"(a[1]), "r"(a[2]), "r"(a[3]), "r"(b[0]), "r"(b[1]));
}

__device__ __forceinline__ uint32_t cvt2h(float x, float y) {
    __half2 h = __floats2half2_rn(x, y);
    return *reinterpret_cast<uint32_t*>(&h);
}

__device__ __forceinline__ void cp16(uint32_t dst, const void* src, uint32_t srcbytes) {
    asm volatile("cp.async.cg.shared.global [%0], [%1], 16, %2;"
                 :: "r"(dst), "l"(src), "r"(srcbytes) : "memory");
}
#define CP_COMMIT() asm volatile("cp.async.commit_group;" ::: "memory")
#define CP_WAIT(N)  asm volatile("cp.async.wait_group %0;" :: "n"(N) : "memory")

// ---------------------------------------------------------------------------
// merged fp32 -> fp16 conversion (one launch for X, W1, W2)
// ---------------------------------------------------------------------------
#define XN4 (XN / 4)
#define W1N4 (W1N / 4)
#define W2N4 (W2N / 4)
#define CVT_TOTAL4 (XN4 + W1N4 + W2N4)

__global__ void cvt_all_kernel(const float* __restrict__ x, __half* __restrict__ xh,
                               const float* __restrict__ w1, __half* __restrict__ w1h,
                               const float* __restrict__ w2, __half* __restrict__ w2h) {
    int i = blockIdx.x * 256 + threadIdx.x;
    if (i >= CVT_TOTAL4) return;
    const float* in;
    __half* outp;
    int j = i;
    if (j < XN4) { in = x; outp = xh; }
    else if (j < XN4 + W1N4) { j -= XN4; in = w1; outp = w1h; }
    else { j -= XN4 + W1N4; in = w2; outp = w2h; }
    float4 v = reinterpret_cast<const float4*>(in)[j];
    reinterpret_cast<uint2*>(outp)[j] = make_uint2(cvt2h(v.x, v.y), cvt2h(v.z, v.w));
}

// ---------------------------------------------------------------------------
// bias precompute: biasP[h][q][p] = fp16x2( bias[q][2p], bias[q][2p+1] )
// invalid k (>=NQ) -> -inf (fp16); q rows >= NQ replicate row NQ-1.
// ---------------------------------------------------------------------------
__global__ void bias_pre_kernel(const float* __restrict__ rpb,
                                const int* __restrict__ ridx,
                                uint32_t* __restrict__ biasP) {
    int h = blockIdx.x / NQP;
    int q = blockIdx.x % NQP;
    int p = threadIdx.x;                       // 0..103
    int qq = min(q, NQ - 1);
    int n0 = 2 * p, n1 = 2 * p + 1;
    float b0 = (n0 < NQ) ? rpb[(size_t)ridx[(size_t)qq * NQ + n0] * NH + h] : -1e30f;
    float b1 = (n1 < NQ) ? rpb[(size_t)ridx[(size_t)qq * NQ + n1] * NH + h] : -1e30f;
    biasP[((size_t)h * NQP + q) * BPQ + p] = cvt2h(b0, b1);   // -1e30 -> fp16 -inf
}

// ---------------------------------------------------------------------------
// single-fp16 GEMM (exact R14 config): CTA 128x128, 8 warps (warp 64x32),
// BK=64 per stage, 2-stage cp.async, ONE sync per 64-K chunk, 2 CTAs/SM.
// ---------------------------------------------------------------------------
#define STRD 144                     // bytes per smem row (128 data + 16 pad)
#define TILEH (128 * STRD)           // 18432 B per matrix per stage
#define STGH  (2 * TILEH)            // 36864 B per stage (A + B)
#define GSH_TOTAL (2 * STGH)         // 73728 B (x2 CTAs = 147456 <= 228K)
#define NKT2 (DIM / 64)              // 12

template <typename Epi>
__global__ __launch_bounds__(256, 2)
void hgemm(const __half* __restrict__ Ah, const __half* __restrict__ Bh,
           int M, Epi epi) {
    extern __shared__ char smem[];
    const uint32_t sb = smem_u32(smem);
    const int tid = threadIdx.x;
    const int warp = tid >> 5;
    const int lane = tid & 31;
    const int wm = warp >> 2;
    const int wn = warp & 3;
    const int m0 = blockIdx.y * 128;
    const int n0 = blockIdx.x * 128;

    float acc[4][4][4];
#pragma unroll
    for (int i = 0; i < 4; i++)
#pragma unroll
        for (int j = 0; j < 4; j++)
#pragma unroll
            for (int k = 0; k < 4; k++) acc[i][j][k] = 0.f;

    uint32_t aoff[4], boff[2];
#pragma unroll
    for (int mf = 0; mf < 4; mf++)
        aoff[mf] = (uint32_t)((wm * 64 + mf * 16 + (lane & 15)) * STRD + (lane >> 4) * 16);
#pragma unroll
    for (int pr = 0; pr < 2; pr++)
        boff[pr] = (uint32_t)(TILEH +
                   (wn * 32 + pr * 16 + ((lane >> 4) * 8) + (lane & 7)) * STRD +
                   ((lane >> 3) & 1) * 16);

    auto load_stage = [&](int kt) {
        const uint32_t sbase = sb + (uint32_t)((kt & 1) * STGH);
#pragma unroll
        for (int i = 0; i < 8; i++) {
            int id = tid + 256 * i;              // 0..2047
            int mat = id >> 10;                  // 0 = A, 1 = B
            int r = (id & 1023) >> 3;            // 0..127
            int c4 = id & 7;
            uint32_t dst = sbase + (uint32_t)(mat * TILEH + r * STRD + c4 * 16);
            if (mat == 0) {
                int m = m0 + r;
                int mc = (m < M) ? m : 0;
                uint32_t sz = (m < M) ? 16u : 0u;
                cp16(dst, Ah + (size_t)mc * DIM + kt * 64 + c4 * 8, sz);
            } else {
                cp16(dst, Bh + (size_t)(n0 + r) * DIM + kt * 64 + c4 * 8, 16u);
            }
        }
        CP_COMMIT();
    };

    auto compute = [&](int st) {
        const uint32_t sadd = sb + (uint32_t)(st * STGH);
#pragma unroll
        for (int ks = 0; ks < 4; ks++) {
            uint32_t bh[4][2];
#pragma unroll
            for (int pr = 0; pr < 2; pr++) {
                uint32_t t[4];
                ldsm4(t, sadd + boff[pr] + ks * 32);
                bh[2 * pr][0] = t[0]; bh[2 * pr][1] = t[1];
                bh[2 * pr + 1][0] = t[2]; bh[2 * pr + 1][1] = t[3];
            }
#pragma unroll
            for (int mf = 0; mf < 4; mf++) {
                uint32_t ah[4];
                ldsm4(ah, sadd + aoff[mf] + ks * 32);
#pragma unroll
                for (int nf = 0; nf < 4; nf++) mma16816(acc[mf][nf], ah, bh[nf]);
            }
        }
    };

    load_stage(0);

    for (int kt = 0; kt < NKT2; kt++) {
        CP_WAIT(0);
        __syncthreads();
        if (kt + 1 < NKT2) load_stage(kt + 1);
        compute(kt & 1);
    }

    const int g = lane >> 2;
    const int tig = lane & 3;
#pragma unroll
    for (int mf = 0; mf < 4; mf++) {
#pragma unroll
        for (int nf = 0; nf < 4; nf++) {
            int m = m0 + wm * 64 + mf * 16 + g;
            int n = n0 + wn * 32 + nf * 8 + tig * 2;
            if (m < M)     epi(m, n, make_float2(acc[mf][nf][0], acc[mf][nf][1]));
            if (m + 8 < M) epi(m + 8, n, make_float2(acc[mf][nf][2], acc[mf][nf][3]));
        }
    }
}

struct QKVEpiH {
    const float* qb;
    const float* vb;
    __half *Qh, *Kh, *Vh;
    __device__ __forceinline__ void operator()(int m, int n, float2 v) const {
        int part = n / DIM;
        int c = n - part * DIM;
        int h = c >> 6;
        int d = c & 63;
        int b = m / NQ;
        int r = m - b * NQ;
        size_t idx = ((size_t)((b * NH + h) * NQ + r)) * HD + d;
        if (part == 0) {
            *reinterpret_cast<uint32_t*>(Qh + idx) =
                cvt2h((v.x + qb[c]) * 0.125f, (v.y + qb[c + 1]) * 0.125f);
        } else if (part == 1) {
            *reinterpret_cast<uint32_t*>(Kh + idx) = cvt2h(v.x, v.y);
        } else {
            *reinterpret_cast<uint32_t*>(Vh + idx) = cvt2h(v.x + vb[c], v.y + vb[c + 1]);
        }
    }
};

struct ProjEpi2 {
    const float* pb;
    float* out;
    __device__ __forceinline__ void operator()(int m, int n, float2 v) const {
        v.x += pb[n];
        v.y += pb[n + 1];
        *reinterpret_cast<float2*>(out + (size_t)m * DIM + n) = v;
    }
};

// ---------------------------------------------------------------------------
// Tensor-core attention, single fp16, precomputed fp16x2 bias table.
// 13 warps, 1 q-block per warp. Masking comes from -inf bias entries.
// ---------------------------------------------------------------------------
#define ATHREADS 416
#define KSTR_B 144
#define AMAT_B (NQP * KSTR_B)
#define ASMEM_TOTAL (3 * AMAT_B)     // 89856 (no tab array any more)

__global__ __launch_bounds__(ATHREADS, 1)
void attn_mma(const __half* __restrict__ Qh,
              const __half* __restrict__ Kh, const __half* __restrict__ Vh,
              const uint32_t* __restrict__ biasP,
              __half* __restrict__ AOh) {
    extern __shared__ char sm[];
    const uint32_t sb = smem_u32(sm);
    const uint32_t sQ = sb;
    const uint32_t sK = sb + 1 * AMAT_B;
    const uint32_t sV = sb + 2 * AMAT_B;

    const int bh = blockIdx.x;
    const int h = bh % NH;
    const int b = bh / NH;
    const int tid = threadIdx.x;
    const int warp = tid >> 5;
    const int lane = tid & 31;
    const int g = lane >> 2;
    const int tig = lane & 3;
    const size_t base = (size_t)bh * NQ * HD;

    // zero pad rows 197..207 in all three arrays
    for (int i = tid; i < 11 * 9; i += ATHREADS) {
        int r = 197 + i / 9;
        int c = i % 9;
        uint32_t off = (uint32_t)(r * KSTR_B + c * 16);
#pragma unroll
        for (int a = 0; a < 3; a++)
            *reinterpret_cast<uint4*>(sm + a * AMAT_B + off) = make_uint4(0u, 0u, 0u, 0u);
    }
    for (int c = tid; c < NQ * 8; c += ATHREADS) {
        int r = c >> 3;
        int col = c & 7;
        uint32_t doff = (uint32_t)(r * KSTR_B + col * 16);
        size_t ga = base + (size_t)r * HD + col * 8;
        cp16(sQ + doff, Qh + ga, 16u);
        cp16(sK + doff, Kh + ga, 16u);
        cp16(sV + doff, Vh + ga, 16u);
    }
    CP_COMMIT();
    CP_WAIT(0);
    __syncthreads();

    {
        const int blk = warp;
        float s[26][4];
#pragma unroll
        for (int nc = 0; nc < 26; nc++)
#pragma unroll
            for (int e = 0; e < 4; e++) s[nc][e] = 0.f;

        const uint32_t qrow = (uint32_t)((blk * 16 + (lane & 15)) * KSTR_B + (lane >> 4) * 16);
        const uint32_t krow = (uint32_t)(((lane >> 4) * 8 + (lane & 7)) * KSTR_B + ((lane >> 3) & 1) * 16);

#pragma unroll
        for (int kc = 0; kc < 4; kc++) {
            uint32_t qh[4];
            ldsm4(qh, sQ + qrow + kc * 32);
#pragma unroll
            for (int np = 0; np < 13; np++) {
                uint32_t th[4];
                ldsm4(th, sK + krow + (uint32_t)(np * 16 * KSTR_B) + kc * 32);
                mma16816(s[2 * np],     qh, th);
                mma16816(s[2 * np + 1], qh, th + 2);
            }
        }

        // precomputed bias (fp16x2 pairs; -inf marks invalid keys)
        const int q0 = blk * 16 + g;
        const int q1 = q0 + 8;
        const uint32_t* bp0 = biasP + ((size_t)h * NQP + q0) * BPQ;
        const uint32_t* bp1 = biasP + ((size_t)h * NQP + q1) * BPQ;
#pragma unroll
        for (int nc = 0; nc < 26; nc++) {
            __half2 h0 = *reinterpret_cast<const __half2*>(bp0 + nc * 4 + tig);
            __half2 h1 = *reinterpret_cast<const __half2*>(bp1 + nc * 4 + tig);
            s[nc][0] += __low2float(h0);
            s[nc][1] += __high2float(h0);
            s[nc][2] += __low2float(h1);
            s[nc][3] += __high2float(h1);
        }

        float mx0 = -1e30f, mx1 = -1e30f;
#pragma unroll
        for (int nc = 0; nc < 26; nc++) {
            mx0 = fmaxf(mx0, fmaxf(s[nc][0], s[nc][1]));
            mx1 = fmaxf(mx1, fmaxf(s[nc][2], s[nc][3]));
        }
        mx0 = fmaxf(mx0, __shfl_xor_sync(0xffffffffu, mx0, 1));
        mx0 = fmaxf(mx0, __shfl_xor_sync(0xffffffffu, mx0, 2));
        mx1 = fmaxf(mx1, __shfl_xor_sync(0xffffffffu, mx1, 1));
        mx1 = fmaxf(mx1, __shfl_xor_sync(0xffffffffu, mx1, 2));

        float sum0 = 0.f, sum1 = 0.f;
#pragma unroll
        for (int nc = 0; nc < 26; nc++) {
            s[nc][0] = __expf(s[nc][0] - mx0);
            s[nc][1] = __expf(s[nc][1] - mx0);
            s[nc][2] = __expf(s[nc][2] - mx1);
            s[nc][3] = __expf(s[nc][3] - mx1);
            sum0 += s[nc][0] + s[nc][1];
            sum1 += s[nc][2] + s[nc][3];
        }
        sum0 += __shfl_xor_sync(0xffffffffu, sum0, 1);
        sum0 += __shfl_xor_sync(0xffffffffu, sum0, 2);
        sum1 += __shfl_xor_sync(0xffffffffu, sum1, 1);
        sum1 += __shfl_xor_sync(0xffffffffu, sum1, 2);
        float inv0 = __frcp_rn(sum0);
        float inv1 = __frcp_rn(sum1);
#pragma unroll
        for (int nc = 0; nc < 26; nc++) {
            s[nc][0] *= inv0; s[nc][1] *= inv0;
            s[nc][2] *= inv1; s[nc][3] *= inv1;
        }

        float o[8][4];
#pragma unroll
        for (int nd = 0; nd < 8; nd++)
#pragma unroll
            for (int e = 0; e < 4; e++) o[nd][e] = 0.f;

        const uint32_t vrow = (uint32_t)((((lane >> 3) & 1) * 8 + (lane & 7)) * KSTR_B + (lane >> 4) * 16);

#pragma unroll
        for (int kc = 0; kc < 13; kc++) {
            uint32_t ph[4];
            ph[0] = cvt2h(s[2 * kc][0],     s[2 * kc][1]);
            ph[1] = cvt2h(s[2 * kc][2],     s[2 * kc][3]);
            ph[2] = cvt2h(s[2 * kc + 1][0], s[2 * kc + 1][1]);
            ph[3] = cvt2h(s[2 * kc + 1][2], s[2 * kc + 1][3]);
#pragma unroll
            for (int dg = 0; dg < 4; dg++) {
                uint32_t vh4[4];
                ldsm4t(vh4, sV + vrow + (uint32_t)(kc * 16 * KSTR_B) + dg * 32);
                mma16816(o[2 * dg],     ph, vh4);
                mma16816(o[2 * dg + 1], ph, vh4 + 2);
            }
        }

        if (q0 < NQ) {
            size_t ob = ((size_t)(b * NQ + q0) * NH + h) * HD + tig * 2;
#pragma unroll
            for (int nd = 0; nd < 8; nd++)
                *reinterpret_cast<uint32_t*>(AOh + ob + nd * 8) = cvt2h(o[nd][0], o[nd][1]);
        }
        if (q1 < NQ) {
            size_t ob = ((size_t)(b * NQ + q1) * NH + h) * HD + tig * 2;
#pragma unroll
            for (int nd = 0; nd < 8; nd++)
                *reinterpret_cast<uint32_t*>(AOh + ob + nd * 8) = cvt2h(o[nd][2], o[nd][3]);
        }
    }
}

// ---------------------------------------------------------------------------
extern "C" void kernel_launch(void* const* d_in, const int* in_sizes, int n_in,
                              void* d_out, int out_size) {
    const float* x      = (const float*)d_in[0];
    const float* qkv_w  = (const float*)d_in[1];
    const float* q_bias = (const float*)d_in[2];
    const float* v_bias = (const float*)d_in[3];
    const float* rpb    = (const float*)d_in[4];
    const float* proj_w = (const float*)d_in[5];
    const float* proj_b = (const float*)d_in[6];
    const int*   ridx   = (const int*)d_in[7];
    float* out = (float*)d_out;

    __half *Xh, *W1h, *W2h, *Qh, *Kh, *Vh, *AOh;
    uint32_t* biasP;
    cudaGetSymbolAddress((void**)&Xh, g_Xh);
    cudaGetSymbolAddress((void**)&W1h, g_W1h);
    cudaGetSymbolAddress((void**)&W2h, g_W2h);
    cudaGetSymbolAddress((void**)&Qh, g_Qh);
    cudaGetSymbolAddress((void**)&Kh, g_Kh);
    cudaGetSymbolAddress((void**)&Vh, g_Vh);
    cudaGetSymbolAddress((void**)&AOh, g_AOh);
    cudaGetSymbolAddress((void**)&biasP, g_biasP);

    cudaFuncSetAttribute(hgemm<QKVEpiH>, cudaFuncAttributeMaxDynamicSharedMemorySize, GSH_TOTAL);
    cudaFuncSetAttribute(hgemm<ProjEpi2>, cudaFuncAttributeMaxDynamicSharedMemorySize, GSH_TOTAL);
    cudaFuncSetAttribute(attn_mma, cudaFuncAttributeMaxDynamicSharedMemorySize, ASMEM_TOTAL);

    // 0) merged fp32 -> fp16 conversion + bias table precompute
    cvt_all_kernel<<<(CVT_TOTAL4 + 255) / 256, 256>>>(x, Xh, qkv_w, W1h, proj_w, W2h);
    bias_pre_kernel<<<NH * NQP, BPQ>>>(rpb, ridx, biasP);

    // 1) fused QKV projection (single fp16, BK=64, 2-stage — R14 config)
    QKVEpiH e1{q_bias, v_bias, Qh, Kh, Vh};
    hgemm<QKVEpiH><<<dim3(3 * DIM / 128, (MROWS + 127) / 128), 256, GSH_TOTAL>>>(
        Xh, W1h, MROWS, e1);

    // 2) attention (single fp16, precomputed bias table)
    attn_mma<<<BATCH * NH, ATHREADS, ASMEM_TOTAL>>>(Qh, Kh, Vh, biasP, AOh);

    // 3) output projection (single fp16, BK=64, 2-stage — R14 config)
    ProjEpi2 e2{proj_b, out};
    hgemm<ProjEpi2><<<dim3(DIM / 128, (MROWS + 127) / 128), 256, GSH_TOTAL>>>(
        AOh, W2h, MROWS, e2);
}